// round 14
// baseline (speedup 1.0000x reference)
#include <cuda_runtime.h>
#include <cstdint>

// FSQCodebook: out[n] = sum_k (round(tanh(x[n,:]·W[k,:] + b[k]) * SCALE) + 1) * 3^k
// x: (65536, 1280) f32, W: (8, 1280) f32, b: (8) f32, out: 65536 (stored as f32)
//
// Warp = 4 rows, k-packed FFMA2 compute (R11). x is streamed through a
// per-warp 4-deep cp.async.cg smem ring (stage = 4 rows x 128 cols = 2 KB),
// decoupling DRAM loads from the register scoreboard / FFMA walls.

#define NDIM_ 8
#define KP_ 4                              // k-pairs
#define KDIM_ 1280
#define ROWS_PER_WARP 4
#define THREADS_ 256
#define WARPS_ (THREADS_ / 32)
#define ROWS_PER_BLOCK (ROWS_PER_WARP * WARPS_)   // 32
#define NROWS_ 65536
#define NITER_ (KDIM_ / 128)               // 10
#define DEPTH_ 4
#define STAGE_FLOATS (ROWS_PER_WARP * 128) // 512 floats = 2 KB
#define SCALE_F 0.9990000128746033f

// Dynamic smem layout
#define WP_BYTES   (KP_ * KDIM_ * 8)                       // 40960
#define BSM_OFF    WP_BYTES                                // +64 pad
#define XBUF_OFF   (WP_BYTES + 64)
#define XBUF_BYTES (WARPS_ * DEPTH_ * STAGE_FLOATS * 4)    // 65536
#define SMEM_TOTAL (XBUF_OFF + XBUF_BYTES)                 // 106560

typedef unsigned long long ull;

__device__ __forceinline__ void ffma2(ull& d, ull a, ull b) {
    asm("fma.rn.f32x2 %0, %1, %2, %0;" : "+l"(d) : "l"(a), "l"(b));
}
__device__ __forceinline__ ull add2(ull a, ull b) {
    ull d;
    asm("add.rn.f32x2 %0, %1, %2;" : "=l"(d) : "l"(a), "l"(b));
    return d;
}
__device__ __forceinline__ ull dup2(float v) {
    ull d;
    asm("mov.b64 %0, {%1, %1};" : "=l"(d) : "f"(v));
    return d;
}
__device__ __forceinline__ ull packf2(float lo, float hi) {
    ull d;
    asm("mov.b64 %0, {%1, %2};" : "=l"(d) : "f"(lo), "f"(hi));
    return d;
}
__device__ __forceinline__ void unpack2(ull v, float& lo, float& hi) {
    asm("mov.b64 {%0, %1}, %2;" : "=f"(lo), "=f"(hi) : "l"(v));
}
__device__ __forceinline__ void cp16(uint32_t dst, const void* src) {
    asm volatile("cp.async.cg.shared.global [%0], [%1], 16;"
                 :: "r"(dst), "l"(src) : "memory");
}
__device__ __forceinline__ void cp_commit() {
    asm volatile("cp.async.commit_group;" ::: "memory");
}
template <int N>
__device__ __forceinline__ void cp_wait() {
    asm volatile("cp.async.wait_group %0;" :: "n"(N) : "memory");
}

__global__ __launch_bounds__(THREADS_, 2)
void fsq_kernel(const float* __restrict__ x,
                const float* __restrict__ W,
                const float* __restrict__ b,
                float* __restrict__ out) {
    extern __shared__ __align__(16) unsigned char dynsm[];
    ull*   Wp   = reinterpret_cast<ull*>(dynsm);
    float* bsm  = reinterpret_cast<float*>(dynsm + BSM_OFF);
    float* xbuf = reinterpret_cast<float*>(dynsm + XBUF_OFF);

    const int tid  = threadIdx.x;
    const int warp = tid >> 5;
    const int lane = tid & 31;
    const int row0 = blockIdx.x * ROWS_PER_BLOCK + warp * ROWS_PER_WARP;

    // Per-warp x ring: base addresses
    float* xw = xbuf + warp * (DEPTH_ * STAGE_FLOATS);
    const uint32_t xw_u32 =
        (uint32_t)__cvta_generic_to_shared(xw) + (uint32_t)lane * 16u;
    const float* xg = x + (size_t)row0 * KDIM_ + lane * 4;

    // Prologue: issue stages 0..3 before anything else (start DRAM early).
    #pragma unroll
    for (int i = 0; i < DEPTH_; ++i) {
        #pragma unroll
        for (int r = 0; r < ROWS_PER_WARP; ++r)
            cp16(xw_u32 + (uint32_t)(i * STAGE_FLOATS + r * 128) * 4u,
                 xg + (size_t)r * KDIM_ + i * 128);
        cp_commit();
    }

    // Stage W packed: Wp[kp*KDIM + c] = (W[2kp][c], W[2kp+1][c]).
    #pragma unroll
    for (int i = 0; i < (KP_ * KDIM_) / THREADS_; ++i) {     // 20
        const int idx = i * THREADS_ + tid;
        const int kp = idx / KDIM_;
        const int c  = idx - kp * KDIM_;
        Wp[idx] = packf2(W[(2 * kp) * KDIM_ + c], W[(2 * kp + 1) * KDIM_ + c]);
    }
    if (tid < NDIM_) bsm[tid] = b[tid];
    __syncthreads();

    // acc[r][kp]: lo = dim 2kp, hi = dim 2kp+1 (32 regs).
    ull acc[ROWS_PER_WARP][KP_];
    #pragma unroll
    for (int r = 0; r < ROWS_PER_WARP; ++r)
        #pragma unroll
        for (int kp = 0; kp < KP_; ++kp)
            acc[r][kp] = 0ull;

    #pragma unroll
    for (int i = 0; i < NITER_; ++i) {
        // Wait for stage i (ring depth 4; tail stages need tighter waits).
        if      (i == NITER_ - 1) cp_wait<0>();
        else if (i == NITER_ - 2) cp_wait<1>();
        else if (i == NITER_ - 3) cp_wait<2>();
        else                      cp_wait<3>();
        __syncwarp();

        const int s = i & (DEPTH_ - 1);
        const float* xs = xw + s * STAGE_FLOATS + lane * 4;

        // x: lane's 4 columns per row (LDS.128, 16 B stride, conflict-free)
        ull xd[ROWS_PER_WARP][4];
        #pragma unroll
        for (int r = 0; r < ROWS_PER_WARP; ++r) {
            const float4 xv = *reinterpret_cast<const float4*>(xs + r * 128);
            xd[r][0] = dup2(xv.x); xd[r][1] = dup2(xv.y);
            xd[r][2] = dup2(xv.z); xd[r][3] = dup2(xv.w);
        }

        #pragma unroll
        for (int kp = 0; kp < KP_; ++kp) {
            const ulonglong2 wA = *reinterpret_cast<const ulonglong2*>(
                Wp + kp * KDIM_ + i * 128 + lane * 4);
            const ulonglong2 wB = *reinterpret_cast<const ulonglong2*>(
                Wp + kp * KDIM_ + i * 128 + lane * 4 + 2);
            #pragma unroll
            for (int r = 0; r < ROWS_PER_WARP; ++r) {
                ffma2(acc[r][kp], xd[r][0], wA.x);
                ffma2(acc[r][kp], xd[r][1], wA.y);
                ffma2(acc[r][kp], xd[r][2], wB.x);
                ffma2(acc[r][kp], xd[r][3], wB.y);
            }
        }

        __syncwarp();   // all lanes done reading stage s before refill
        if (i + DEPTH_ < NITER_) {
            #pragma unroll
            for (int r = 0; r < ROWS_PER_WARP; ++r)
                cp16(xw_u32 + (uint32_t)(s * STAGE_FLOATS + r * 128) * 4u,
                     xg + (size_t)r * KDIM_ + (i + DEPTH_) * 128);
            cp_commit();
        }
    }

    // Warp reduction (packed butterfly); lane r keeps row r's 4 k-pairs.
    ull hp[KP_];
    #pragma unroll
    for (int kp = 0; kp < KP_; ++kp) hp[kp] = 0ull;

    #pragma unroll
    for (int r = 0; r < ROWS_PER_WARP; ++r) {
        #pragma unroll
        for (int kp = 0; kp < KP_; ++kp) {
            ull v = acc[r][kp];
            #pragma unroll
            for (int off = 16; off > 0; off >>= 1)
                v = add2(v, __shfl_xor_sync(0xffffffffu, v, off));
            if (lane == r) hp[kp] = v;
        }
    }

    // Epilogue: lanes 0..3 hold valid hp; all lanes execute, 4 write.
    float mu = 0.0f, p = 1.0f;
    #pragma unroll
    for (int kp = 0; kp < KP_; ++kp) {
        float hlo, hhi;
        unpack2(hp[kp], hlo, hhi);
        {
            float t = tanhf(hlo + bsm[2 * kp]) * SCALE_F;
            mu = fmaf(rintf(t) + 1.0f, p, mu);
            p *= 3.0f;
        }
        {
            float t = tanhf(hhi + bsm[2 * kp + 1]) * SCALE_F;
            mu = fmaf(rintf(t) + 1.0f, p, mu);
            p *= 3.0f;
        }
    }
    if (lane < ROWS_PER_WARP)
        out[row0 + lane] = mu;          // 0..6560 exact in fp32
}

extern "C" void kernel_launch(void* const* d_in, const int* in_sizes, int n_in,
                              void* d_out, int out_size) {
    // Bind inputs by element count (robust to metadata ordering):
    //   x: 65536*1280 = 83886080, W: 8*1280 = 10240, b: 8
    const float* x = nullptr;
    const float* W = nullptr;
    const float* b = nullptr;
    for (int i = 0; i < n_in; ++i) {
        if (in_sizes[i] == NROWS_ * KDIM_)      x = (const float*)d_in[i];
        else if (in_sizes[i] == NDIM_ * KDIM_)  W = (const float*)d_in[i];
        else if (in_sizes[i] == NDIM_)          b = (const float*)d_in[i];
    }
    float* out = (float*)d_out;
    (void)out_size;

    cudaFuncSetAttribute(fsq_kernel,
                         cudaFuncAttributeMaxDynamicSharedMemorySize,
                         SMEM_TOTAL);
    const int blocks = NROWS_ / ROWS_PER_BLOCK;   // 2048
    fsq_kernel<<<blocks, THREADS_, SMEM_TOTAL>>>(x, W, b, out);
}

// round 15
// speedup vs baseline: 1.0276x; 1.0276x over previous
#include <cuda_runtime.h>
#include <cstdint>

// FSQCodebook: out[n] = sum_k (round(tanh(x[n,:]·W[k,:] + b[k]) * SCALE) + 1) * 3^k
// x: (65536, 1280) f32, W: (8, 1280) f32, b: (8) f32, out: 65536 (stored as f32)
//
// R11 structure (warp = 4 rows, k-packed FFMA2, acc = 32 regs, 3 CTAs/SM)
// + per-warp L2 prefetch prologue: the warp's 4 rows are 20 KB contiguous;
// 5 warp-wide prefetch.global.L2 ops cover it, so mainloop LDGs hit L2.

#define NDIM_ 8
#define KP_ 4                              // k-pairs
#define KDIM_ 1280
#define ROWS_PER_WARP 4
#define THREADS_ 256
#define WARPS_ (THREADS_ / 32)
#define ROWS_PER_BLOCK (ROWS_PER_WARP * WARPS_)   // 32
#define NROWS_ 65536
#define NITER_ (KDIM_ / 128)               // 10
#define SCALE_F 0.9990000128746033f

typedef unsigned long long ull;

__device__ __forceinline__ void ffma2(ull& d, ull a, ull b) {
    asm("fma.rn.f32x2 %0, %1, %2, %0;" : "+l"(d) : "l"(a), "l"(b));
}
__device__ __forceinline__ ull add2(ull a, ull b) {
    ull d;
    asm("add.rn.f32x2 %0, %1, %2;" : "=l"(d) : "l"(a), "l"(b));
    return d;
}
__device__ __forceinline__ ull dup2(float v) {
    ull d;
    asm("mov.b64 %0, {%1, %1};" : "=l"(d) : "f"(v));
    return d;
}
__device__ __forceinline__ ull packf2(float lo, float hi) {
    ull d;
    asm("mov.b64 %0, {%1, %2};" : "=l"(d) : "f"(lo), "f"(hi));
    return d;
}
__device__ __forceinline__ void unpack2(ull v, float& lo, float& hi) {
    asm("mov.b64 {%0, %1}, %2;" : "=f"(lo), "=f"(hi) : "l"(v));
}
__device__ __forceinline__ void pf_l2(const void* p) {
    asm volatile("prefetch.global.L2 [%0];" :: "l"(p));
}

__global__ __launch_bounds__(THREADS_, 3)
void fsq_kernel(const float* __restrict__ x,
                const float* __restrict__ W,
                const float* __restrict__ b,
                float* __restrict__ out) {
    __shared__ __align__(16) ull Wp[KP_ * KDIM_];   // 40 KB packed k-pairs
    __shared__ float bsm[NDIM_];

    const int tid  = threadIdx.x;
    const int warp = tid >> 5;
    const int lane = tid & 31;
    const int row0 = blockIdx.x * ROWS_PER_BLOCK + warp * ROWS_PER_WARP;

    // L2 prefetch prologue: warp's x block is 4 rows x 5120 B = 20480 B
    // contiguous = 160 lines of 128 B; 5 warp-wide prefetches cover it.
    {
        const char* xbase = reinterpret_cast<const char*>(x) +
                            (size_t)row0 * KDIM_ * 4;
        #pragma unroll
        for (int i = 0; i < 5; ++i)
            pf_l2(xbase + (size_t)(i * 32 + lane) * 128);
    }

    // Stage W packed: Wp[kp*KDIM + c] = (W[2kp][c], W[2kp+1][c]).
    #pragma unroll
    for (int i = 0; i < (KP_ * KDIM_) / THREADS_; ++i) {     // 20
        const int idx = i * THREADS_ + tid;
        const int kp = idx / KDIM_;
        const int c  = idx - kp * KDIM_;
        Wp[idx] = packf2(W[(2 * kp) * KDIM_ + c], W[(2 * kp + 1) * KDIM_ + c]);
    }
    if (tid < NDIM_) bsm[tid] = b[tid];
    __syncthreads();

    const float* xr = x + (size_t)row0 * KDIM_ + lane * 2;

    // acc[r][kp]: lo accumulates dim 2kp, hi accumulates dim 2kp+1 (32 regs).
    ull acc[ROWS_PER_WARP][KP_];
    #pragma unroll
    for (int r = 0; r < ROWS_PER_WARP; ++r)
        #pragma unroll
        for (int kp = 0; kp < KP_; ++kp)
            acc[r][kp] = 0ull;

    #pragma unroll
    for (int i = 0; i < NITER_; ++i) {
        // x: lane's 2 column-pairs per row: cols i*128 + {2l,2l+1} and +64.
        float2 xa[ROWS_PER_WARP], xb[ROWS_PER_WARP];
        #pragma unroll
        for (int r = 0; r < ROWS_PER_WARP; ++r) {
            xa[r] = *reinterpret_cast<const float2*>(xr + r * KDIM_ + i * 128);
            xb[r] = *reinterpret_cast<const float2*>(xr + r * KDIM_ + i * 128 + 64);
        }

        // Broadcast each x value into both halves (16 packs).
        ull x0[ROWS_PER_WARP], x1[ROWS_PER_WARP], x2[ROWS_PER_WARP], x3[ROWS_PER_WARP];
        #pragma unroll
        for (int r = 0; r < ROWS_PER_WARP; ++r) {
            x0[r] = dup2(xa[r].x);  x1[r] = dup2(xa[r].y);
            x2[r] = dup2(xb[r].x);  x3[r] = dup2(xb[r].y);
        }

        #pragma unroll
        for (int kp = 0; kp < KP_; ++kp) {
            // Conflict-free LDS.128: lane stride 16 B within each 128 B row.
            const ulonglong2 wA = *reinterpret_cast<const ulonglong2*>(
                Wp + kp * KDIM_ + i * 128 + lane * 2);
            const ulonglong2 wB = *reinterpret_cast<const ulonglong2*>(
                Wp + kp * KDIM_ + i * 128 + 64 + lane * 2);
            #pragma unroll
            for (int r = 0; r < ROWS_PER_WARP; ++r) {
                ffma2(acc[r][kp], x0[r], wA.x);
                ffma2(acc[r][kp], x1[r], wA.y);
                ffma2(acc[r][kp], x2[r], wB.x);
                ffma2(acc[r][kp], x3[r], wB.y);
            }
        }
    }

    // Warp reduction (packed butterfly); lane r keeps row r's 4 k-pairs.
    ull hp[KP_];
    #pragma unroll
    for (int kp = 0; kp < KP_; ++kp) hp[kp] = 0ull;

    #pragma unroll
    for (int r = 0; r < ROWS_PER_WARP; ++r) {
        #pragma unroll
        for (int kp = 0; kp < KP_; ++kp) {
            ull v = acc[r][kp];
            #pragma unroll
            for (int off = 16; off > 0; off >>= 1)
                v = add2(v, __shfl_xor_sync(0xffffffffu, v, off));
            if (lane == r) hp[kp] = v;
        }
    }

    // Epilogue: lanes 0..3 hold valid hp; all lanes execute, 4 write.
    float mu = 0.0f, p = 1.0f;
    #pragma unroll
    for (int kp = 0; kp < KP_; ++kp) {
        float hlo, hhi;
        unpack2(hp[kp], hlo, hhi);
        {
            float t = tanhf(hlo + bsm[2 * kp]) * SCALE_F;
            mu = fmaf(rintf(t) + 1.0f, p, mu);
            p *= 3.0f;
        }
        {
            float t = tanhf(hhi + bsm[2 * kp + 1]) * SCALE_F;
            mu = fmaf(rintf(t) + 1.0f, p, mu);
            p *= 3.0f;
        }
    }
    if (lane < ROWS_PER_WARP)
        out[row0 + lane] = mu;          // 0..6560 exact in fp32
}

extern "C" void kernel_launch(void* const* d_in, const int* in_sizes, int n_in,
                              void* d_out, int out_size) {
    // Bind inputs by element count (robust to metadata ordering):
    //   x: 65536*1280 = 83886080, W: 8*1280 = 10240, b: 8
    const float* x = nullptr;
    const float* W = nullptr;
    const float* b = nullptr;
    for (int i = 0; i < n_in; ++i) {
        if (in_sizes[i] == NROWS_ * KDIM_)      x = (const float*)d_in[i];
        else if (in_sizes[i] == NDIM_ * KDIM_)  W = (const float*)d_in[i];
        else if (in_sizes[i] == NDIM_)          b = (const float*)d_in[i];
    }
    float* out = (float*)d_out;
    (void)out_size;

    const int blocks = NROWS_ / ROWS_PER_BLOCK;   // 2048
    fsq_kernel<<<blocks, THREADS_>>>(x, W, b, out);
}

// round 17
// speedup vs baseline: 1.0961x; 1.0666x over previous
#include <cuda_runtime.h>
#include <cstdint>

// FSQCodebook: out[n] = sum_k (round(tanh(x[n,:]·W[k,:] + b[k]) * SCALE) + 1) * 3^k
// x: (65536, 1280) f32, W: (8, 1280) f32, b: (8) f32, out: 65536 (stored as f32)
//
// R11 structure (warp = 4 rows, k-packed FFMA2, acc = 32 regs, 3 CTAs/SM).
// x loads use ld.global.cs.L2::256B (evict-first streaming + 256 B L2
// granules): zero extra instructions, less L2 thrash, larger DRAM requests.

#define NDIM_ 8
#define KP_ 4                              // k-pairs
#define KDIM_ 1280
#define ROWS_PER_WARP 4
#define THREADS_ 256
#define WARPS_ (THREADS_ / 32)
#define ROWS_PER_BLOCK (ROWS_PER_WARP * WARPS_)   // 32
#define NROWS_ 65536
#define NITER_ (KDIM_ / 128)               // 10
#define SCALE_F 0.9990000128746033f

typedef unsigned long long ull;

__device__ __forceinline__ void ffma2(ull& d, ull a, ull b) {
    asm("fma.rn.f32x2 %0, %1, %2, %0;" : "+l"(d) : "l"(a), "l"(b));
}
__device__ __forceinline__ ull add2(ull a, ull b) {
    ull d;
    asm("add.rn.f32x2 %0, %1, %2;" : "=l"(d) : "l"(a), "l"(b));
    return d;
}
__device__ __forceinline__ ull dup2(float v) {
    ull d;
    asm("mov.b64 %0, {%1, %1};" : "=l"(d) : "f"(v));
    return d;
}
__device__ __forceinline__ ull packf2(float lo, float hi) {
    ull d;
    asm("mov.b64 %0, {%1, %2};" : "=l"(d) : "f"(lo), "f"(hi));
    return d;
}
__device__ __forceinline__ void unpack2(ull v, float& lo, float& hi) {
    asm("mov.b64 {%0, %1}, %2;" : "=f"(lo), "=f"(hi) : "l"(v));
}
// Streaming x load: evict-first, 256 B L2 fetch granule.
__device__ __forceinline__ float2 ldx2(const float* p) {
    float2 v;
    asm("ld.global.cs.L2::256B.v2.f32 {%0, %1}, [%2];"
        : "=f"(v.x), "=f"(v.y) : "l"(p));
    return v;
}

__global__ __launch_bounds__(THREADS_, 3)
void fsq_kernel(const float* __restrict__ x,
                const float* __restrict__ W,
                const float* __restrict__ b,
                float* __restrict__ out) {
    __shared__ __align__(16) ull Wp[KP_ * KDIM_];   // 40 KB packed k-pairs
    __shared__ float bsm[NDIM_];

    const int tid  = threadIdx.x;
    const int warp = tid >> 5;
    const int lane = tid & 31;
    const int row0 = blockIdx.x * ROWS_PER_BLOCK + warp * ROWS_PER_WARP;

    // Stage W packed: Wp[kp*KDIM + c] = (W[2kp][c], W[2kp+1][c]).
    #pragma unroll
    for (int i = 0; i < (KP_ * KDIM_) / THREADS_; ++i) {     // 20
        const int idx = i * THREADS_ + tid;
        const int kp = idx / KDIM_;
        const int c  = idx - kp * KDIM_;
        Wp[idx] = packf2(W[(2 * kp) * KDIM_ + c], W[(2 * kp + 1) * KDIM_ + c]);
    }
    if (tid < NDIM_) bsm[tid] = b[tid];
    __syncthreads();

    const float* xr = x + (size_t)row0 * KDIM_ + lane * 2;

    // acc[r][kp]: lo accumulates dim 2kp, hi accumulates dim 2kp+1 (32 regs).
    ull acc[ROWS_PER_WARP][KP_];
    #pragma unroll
    for (int r = 0; r < ROWS_PER_WARP; ++r)
        #pragma unroll
        for (int kp = 0; kp < KP_; ++kp)
            acc[r][kp] = 0ull;

    #pragma unroll
    for (int i = 0; i < NITER_; ++i) {
        // x: lane's 2 column-pairs per row: cols i*128 + {2l,2l+1} and +64.
        float2 xa[ROWS_PER_WARP], xb[ROWS_PER_WARP];
        #pragma unroll
        for (int r = 0; r < ROWS_PER_WARP; ++r) {
            xa[r] = ldx2(xr + r * KDIM_ + i * 128);
            xb[r] = ldx2(xr + r * KDIM_ + i * 128 + 64);
        }

        // Broadcast each x value into both halves (16 packs).
        ull x0[ROWS_PER_WARP], x1[ROWS_PER_WARP], x2[ROWS_PER_WARP], x3[ROWS_PER_WARP];
        #pragma unroll
        for (int r = 0; r < ROWS_PER_WARP; ++r) {
            x0[r] = dup2(xa[r].x);  x1[r] = dup2(xa[r].y);
            x2[r] = dup2(xb[r].x);  x3[r] = dup2(xb[r].y);
        }

        #pragma unroll
        for (int kp = 0; kp < KP_; ++kp) {
            // Conflict-free LDS.128: lane stride 16 B within each 128 B row.
            const ulonglong2 wA = *reinterpret_cast<const ulonglong2*>(
                Wp + kp * KDIM_ + i * 128 + lane * 2);
            const ulonglong2 wB = *reinterpret_cast<const ulonglong2*>(
                Wp + kp * KDIM_ + i * 128 + 64 + lane * 2);
            #pragma unroll
            for (int r = 0; r < ROWS_PER_WARP; ++r) {
                ffma2(acc[r][kp], x0[r], wA.x);
                ffma2(acc[r][kp], x1[r], wA.y);
                ffma2(acc[r][kp], x2[r], wB.x);
                ffma2(acc[r][kp], x3[r], wB.y);
            }
        }
    }

    // Warp reduction (packed butterfly); lane r keeps row r's 4 k-pairs.
    ull hp[KP_];
    #pragma unroll
    for (int kp = 0; kp < KP_; ++kp) hp[kp] = 0ull;

    #pragma unroll
    for (int r = 0; r < ROWS_PER_WARP; ++r) {
        #pragma unroll
        for (int kp = 0; kp < KP_; ++kp) {
            ull v = acc[r][kp];
            #pragma unroll
            for (int off = 16; off > 0; off >>= 1)
                v = add2(v, __shfl_xor_sync(0xffffffffu, v, off));
            if (lane == r) hp[kp] = v;
        }
    }

    // Epilogue: lanes 0..3 hold valid hp; all lanes execute, 4 write.
    float mu = 0.0f, p = 1.0f;
    #pragma unroll
    for (int kp = 0; kp < KP_; ++kp) {
        float hlo, hhi;
        unpack2(hp[kp], hlo, hhi);
        {
            float t = tanhf(hlo + bsm[2 * kp]) * SCALE_F;
            mu = fmaf(rintf(t) + 1.0f, p, mu);
            p *= 3.0f;
        }
        {
            float t = tanhf(hhi + bsm[2 * kp + 1]) * SCALE_F;
            mu = fmaf(rintf(t) + 1.0f, p, mu);
            p *= 3.0f;
        }
    }
    if (lane < ROWS_PER_WARP)
        out[row0 + lane] = mu;          // 0..6560 exact in fp32
}

extern "C" void kernel_launch(void* const* d_in, const int* in_sizes, int n_in,
                              void* d_out, int out_size) {
    // Bind inputs by element count (robust to metadata ordering):
    //   x: 65536*1280 = 83886080, W: 8*1280 = 10240, b: 8
    const float* x = nullptr;
    const float* W = nullptr;
    const float* b = nullptr;
    for (int i = 0; i < n_in; ++i) {
        if (in_sizes[i] == NROWS_ * KDIM_)      x = (const float*)d_in[i];
        else if (in_sizes[i] == NDIM_ * KDIM_)  W = (const float*)d_in[i];
        else if (in_sizes[i] == NDIM_)          b = (const float*)d_in[i];
    }
    float* out = (float*)d_out;
    (void)out_size;

    const int blocks = NROWS_ / ROWS_PER_BLOCK;   // 2048
    fsq_kernel<<<blocks, THREADS_>>>(x, W, b, out);
}